// round 16
// baseline (speedup 1.0000x reference)
#include <cuda_runtime.h>
#include <cstdint>
#include <math.h>

#define N_RAYS    65536
#define N_SAMPLES 192
#define NGROUPS   6
#define EPSV      1e-10f
#define WARPS_PER_BLOCK 4
#define THREADS   (WARPS_PER_BLOCK * 32)

// Output layout: flattened tuple concat
//   rgb_map  : [N,3]    offset 0
//   density  : [N,191]  offset N*3
//   acc_map  : [N]      offset N*194
//   weights  : [N,192]  offset N*195
//   depth    : [N]      offset N*387
#define OFF_RGB   0
#define OFF_DENS  (N_RAYS * 3)
#define OFF_ACC   (N_RAYS * 194)
#define OFF_W     (N_RAYS * 195)
#define OFF_DEPTH (N_RAYS * 387)

__device__ __forceinline__ float fast_sigmoid(float x) {
    float t;
    asm("tanh.approx.f32 %0, %1;" : "=f"(t) : "f"(x * 0.5f));
    return fmaf(t, 0.5f, 0.5f);
}

__device__ __forceinline__ void cp_async16(unsigned int smem_addr, const void* gptr) {
    asm volatile("cp.async.cg.shared.global [%0], [%1], 16;"
                 :: "r"(smem_addr), "l"(gptr));
}
__device__ __forceinline__ void cp_commit() {
    asm volatile("cp.async.commit_group;");
}
template <int N>
__device__ __forceinline__ void cp_wait() {
    asm volatile("cp.async.wait_group %0;" :: "n"(N));
}

__global__ __launch_bounds__(THREADS, 16)
void nerf_volrender_kernel(const float4* __restrict__ raw4,
                           const float*  __restrict__ z_vals,
                           const float*  __restrict__ rays_d,
                           float*        __restrict__ out)
{
    const unsigned FULL = 0xFFFFFFFFu;
    const int wib   = threadIdx.x >> 5;
    const int lane  = threadIdx.x & 31;
    const int r     = blockIdx.x * WARPS_PER_BLOCK + wib;   // one warp per ray

    __shared__ float4 sraw[WARPS_PER_BLOCK][N_SAMPLES];     // 12 KB, warp-private

    const int zbase = r * N_SAMPLES;

    // ---- issue 6 raw copies as 3 commit groups of 2 (register-free MLP) ----
    unsigned int sbase = (unsigned int)__cvta_generic_to_shared(&sraw[wib][0]);
    #pragma unroll
    for (int g = 0; g < 3; g++) {
        int s0 = (g * 64) + lane;
        cp_async16(sbase + (unsigned int)s0 * 16u,        &raw4[zbase + s0]);
        cp_async16(sbase + (unsigned int)(s0 + 32) * 16u, &raw4[zbase + s0 + 32]);
        cp_commit();
    }

    // ---- z loads to registers (retire via scoreboard, overlap the copies) ----
    float zv[NGROUPS];
    #pragma unroll
    for (int j = 0; j < NGROUPS; j++)
        zv[j] = __ldcs(&z_vals[zbase + (j << 5) + lane]);

    float dx = __ldg(&rays_d[r * 3 + 0]);
    float dy = __ldg(&rays_d[r * 3 + 1]);
    float dz = __ldg(&rays_d[r * 3 + 2]);
    float dnorm = sqrtf(dx * dx + dy * dy + dz * dz);

    float off = 1.0f;
    float sr = 0.f, sg = 0.f, sb = 0.f, sw = 0.f, sd = 0.f;

    #pragma unroll
    for (int j = 0; j < NGROUPS; j++) {
        // wait for the commit group containing this j (j/2)
        if (j == 0)      { cp_wait<2>(); __syncwarp(); }
        else if (j == 2) { cp_wait<1>(); __syncwarp(); }
        else if (j == 4) { cp_wait<0>(); __syncwarp(); }

        const int s = (j << 5) + lane;
        const float4 rv = sraw[wib][s];                     // LDS.128, conflict-free

        // z[s+1]: shuffle within group; lane 31 takes next group's lane 0
        float zn = __shfl_down_sync(FULL, zv[j], 1);
        if (j < NGROUPS - 1) {
            float znext0 = __shfl_sync(FULL, zv[j + 1], 0);
            if (lane == 31) zn = znext0;
        }
        float dist = fabsf(zn - zv[j]) * dnorm;

        float dens = fmaxf(rv.w, 0.0f);
        if (s < N_SAMPLES - 1)
            __stcs(&out[OFF_DENS + r * (N_SAMPLES - 1) + s], dens);

        bool last = (s == N_SAMPLES - 1);
        float alpha = last ? 1.0f : (1.0f - __expf(-dens * dist));
        float t = (1.0f + EPSV) - alpha;

        // multiplicative inclusive warp scan of t
        float pp = t;
        #pragma unroll
        for (int d = 1; d < 32; d <<= 1) {
            float o = __shfl_up_sync(FULL, pp, d);
            if (lane >= d) pp *= o;
        }

        float excl = __shfl_up_sync(FULL, pp, 1);
        if (lane == 0) excl = 1.0f;
        float trans = off * excl;                    // exclusive cumprod
        float incl  = off * pp;                      // inclusive cumprod
        float w = fmaf(EPSV, trans, trans - incl);   // alpha * trans, exact

        __stcs(&out[OFF_W + r * N_SAMPLES + s], w);

        sr += w * fast_sigmoid(rv.x);
        sg += w * fast_sigmoid(rv.y);
        sb += w * fast_sigmoid(rv.z);
        sw += w;
        sd += w * zv[j];

        off *= __shfl_sync(FULL, pp, 31);
    }

    // warp reduction of the 5 accumulators
    #pragma unroll
    for (int d = 16; d > 0; d >>= 1) {
        sr += __shfl_down_sync(FULL, sr, d);
        sg += __shfl_down_sync(FULL, sg, d);
        sb += __shfl_down_sync(FULL, sb, d);
        sw += __shfl_down_sync(FULL, sw, d);
        sd += __shfl_down_sync(FULL, sd, d);
    }
    if (lane == 0) {
        out[OFF_RGB + r * 3 + 0] = sr;
        out[OFF_RGB + r * 3 + 1] = sg;
        out[OFF_RGB + r * 3 + 2] = sb;
        out[OFF_ACC   + r] = sw;
        out[OFF_DEPTH + r] = sd;
    }
}

extern "C" void kernel_launch(void* const* d_in, const int* in_sizes, int n_in,
                              void* d_out, int out_size)
{
    const float4* raw4   = (const float4*)d_in[0];
    const float*  z_vals = (const float*)d_in[1];
    const float*  rays_d = (const float*)d_in[2];
    float* out = (float*)d_out;

    const int blocks = N_RAYS / WARPS_PER_BLOCK;   // 16384
    nerf_volrender_kernel<<<blocks, THREADS>>>(raw4, z_vals, rays_d, out);
}

// round 17
// speedup vs baseline: 1.0046x; 1.0046x over previous
#include <cuda_runtime.h>
#include <cstdint>
#include <math.h>

#define N_RAYS    65536
#define N_SAMPLES 192
#define NGROUPS   6
#define EPSV      1e-10f
#define WARPS_PER_BLOCK 4
#define THREADS   (WARPS_PER_BLOCK * 32)

// Output layout: flattened tuple concat
//   rgb_map  : [N,3]    offset 0
//   density  : [N,191]  offset N*3
//   acc_map  : [N]      offset N*194
//   weights  : [N,192]  offset N*195
//   depth    : [N]      offset N*387
#define OFF_RGB   0
#define OFF_DENS  (N_RAYS * 3)
#define OFF_ACC   (N_RAYS * 194)
#define OFF_W     (N_RAYS * 195)
#define OFF_DEPTH (N_RAYS * 387)

__device__ __forceinline__ float fast_sigmoid(float x) {
    float t;
    asm("tanh.approx.f32 %0, %1;" : "=f"(t) : "f"(x * 0.5f));
    return fmaf(t, 0.5f, 0.5f);
}

__device__ __forceinline__ void cp_async16(unsigned int smem_addr, const void* gptr) {
    asm volatile("cp.async.cg.shared.global [%0], [%1], 16;"
                 :: "r"(smem_addr), "l"(gptr));
}
__device__ __forceinline__ void cp_commit() {
    asm volatile("cp.async.commit_group;");
}
template <int N>
__device__ __forceinline__ void cp_wait() {
    asm volatile("cp.async.wait_group %0;" :: "n"(N));
}

__global__ __launch_bounds__(THREADS, 16)
void nerf_volrender_kernel(const float4* __restrict__ raw4,
                           const float*  __restrict__ z_vals,
                           const float*  __restrict__ rays_d,
                           float*        __restrict__ out)
{
    const unsigned FULL = 0xFFFFFFFFu;
    const int wib   = threadIdx.x >> 5;
    const int lane  = threadIdx.x & 31;
    const int r     = blockIdx.x * WARPS_PER_BLOCK + wib;   // one warp per ray

    __shared__ float4 sraw[WARPS_PER_BLOCK][N_SAMPLES];     // 12 KB, warp-private

    const int zbase = r * N_SAMPLES;

    // ---- issue 6 raw copies as 3 commit groups of 2 (register-free MLP) ----
    unsigned int sbase = (unsigned int)__cvta_generic_to_shared(&sraw[wib][0]);
    #pragma unroll
    for (int g = 0; g < 3; g++) {
        int s0 = (g * 64) + lane;
        cp_async16(sbase + (unsigned int)s0 * 16u,        &raw4[zbase + s0]);
        cp_async16(sbase + (unsigned int)(s0 + 32) * 16u, &raw4[zbase + s0 + 32]);
        cp_commit();
    }

    // ---- z loads to registers (retire via scoreboard, overlap the copies) ----
    float zv[NGROUPS];
    #pragma unroll
    for (int j = 0; j < NGROUPS; j++)
        zv[j] = __ldcs(&z_vals[zbase + (j << 5) + lane]);

    float dx = __ldg(&rays_d[r * 3 + 0]);
    float dy = __ldg(&rays_d[r * 3 + 1]);
    float dz = __ldg(&rays_d[r * 3 + 2]);
    float dnorm = sqrtf(dx * dx + dy * dy + dz * dz);

    float off = 1.0f;
    float sr = 0.f, sg = 0.f, sb = 0.f, sw = 0.f, sd = 0.f;

    #pragma unroll
    for (int j = 0; j < NGROUPS; j++) {
        // wait for the commit group containing this j (j/2). No __syncwarp
        // needed: each lane reads back only the 16 B it copied itself, and
        // wait_group orders a thread's own async copies with its own loads.
        if (j == 0)      cp_wait<2>();
        else if (j == 2) cp_wait<1>();
        else if (j == 4) cp_wait<0>();

        const int s = (j << 5) + lane;
        const float4 rv = sraw[wib][s];                     // LDS.128, conflict-free

        // z[s+1]: shuffle within group; lane 31 takes next group's lane 0
        float zn = __shfl_down_sync(FULL, zv[j], 1);
        if (j < NGROUPS - 1) {
            float znext0 = __shfl_sync(FULL, zv[j + 1], 0);
            if (lane == 31) zn = znext0;
        }
        float dist = fabsf(zn - zv[j]) * dnorm;

        float dens = fmaxf(rv.w, 0.0f);
        if (s < N_SAMPLES - 1)
            __stcs(&out[OFF_DENS + r * (N_SAMPLES - 1) + s], dens);

        bool last = (s == N_SAMPLES - 1);
        float alpha = last ? 1.0f : (1.0f - __expf(-dens * dist));
        float t = (1.0f + EPSV) - alpha;

        // multiplicative inclusive warp scan of t
        float pp = t;
        #pragma unroll
        for (int d = 1; d < 32; d <<= 1) {
            float o = __shfl_up_sync(FULL, pp, d);
            if (lane >= d) pp *= o;
        }

        float excl = __shfl_up_sync(FULL, pp, 1);
        if (lane == 0) excl = 1.0f;
        float trans = off * excl;                    // exclusive cumprod
        float incl  = off * pp;                      // inclusive cumprod
        float w = fmaf(EPSV, trans, trans - incl);   // alpha * trans, exact

        __stcs(&out[OFF_W + r * N_SAMPLES + s], w);

        sr += w * fast_sigmoid(rv.x);
        sg += w * fast_sigmoid(rv.y);
        sb += w * fast_sigmoid(rv.z);
        sw += w;
        sd += w * zv[j];

        off *= __shfl_sync(FULL, pp, 31);
    }

    // warp reduction of the 5 accumulators
    #pragma unroll
    for (int d = 16; d > 0; d >>= 1) {
        sr += __shfl_down_sync(FULL, sr, d);
        sg += __shfl_down_sync(FULL, sg, d);
        sb += __shfl_down_sync(FULL, sb, d);
        sw += __shfl_down_sync(FULL, sw, d);
        sd += __shfl_down_sync(FULL, sd, d);
    }
    if (lane == 0) {
        out[OFF_RGB + r * 3 + 0] = sr;
        out[OFF_RGB + r * 3 + 1] = sg;
        out[OFF_RGB + r * 3 + 2] = sb;
        out[OFF_ACC   + r] = sw;
        out[OFF_DEPTH + r] = sd;
    }
}

extern "C" void kernel_launch(void* const* d_in, const int* in_sizes, int n_in,
                              void* d_out, int out_size)
{
    const float4* raw4   = (const float4*)d_in[0];
    const float*  z_vals = (const float*)d_in[1];
    const float*  rays_d = (const float*)d_in[2];
    float* out = (float*)d_out;

    const int blocks = N_RAYS / WARPS_PER_BLOCK;   // 16384
    nerf_volrender_kernel<<<blocks, THREADS>>>(raw4, z_vals, rays_d, out);
}